// round 11
// baseline (speedup 1.0000x reference)
#include <cuda_runtime.h>
#include <math_constants.h>

#define N_NODES 20000
#define N_EDGES 640000
#define FIN     128
#define FQK     128
#define FV      128
#define FTOT    384
#define NHEAD   8
#define FH      16
#define BATCH   4      // nodes per work ticket

// ---------------- scratch (device globals; no runtime allocation) ----------
__device__ float g_qkv[N_NODES * FTOT];   // [n][0:128)=q*0.25, [128:256)=k, [256:384)=v
__device__ float g_aw [N_EDGES * NHEAD];  // per-edge per-head logits
__device__ float g_maxw[NHEAD];           // global per-head max
__device__ int   g_dst [N_EDGES];
__device__ int   g_off [N_NODES + 1];     // CSR row offsets over sorted src
__device__ unsigned int g_tick_e;         // work tickets (reset each launch)
__device__ unsigned int g_tick_n;

// ---------------- helpers --------------------------------------------------
__device__ __forceinline__ void atomicMaxF(float* addr, float val) {
    int* ai = (int*)addr;
    int old = *ai;
    while (__int_as_float(old) < val) {
        int assumed = old;
        old = atomicCAS(ai, assumed, __float_as_int(val));
        if (old == assumed) break;
    }
}

__device__ __forceinline__ unsigned long long packdup(float a) {
    unsigned long long r;
    asm("mov.b64 %0, {%1, %1};" : "=l"(r) : "f"(a));
    return r;
}
__device__ __forceinline__ void ffma2(unsigned long long& acc,
                                      unsigned long long a, unsigned long long b) {
    asm("fma.rn.f32x2 %0, %1, %2, %0;" : "+l"(acc) : "l"(a), "l"(b));
}
__device__ __forceinline__ void unpack2(unsigned long long p, float& lo, float& hi) {
    asm("mov.b64 {%0, %1}, %2;" : "=f"(lo), "=f"(hi) : "l"(p));
}

// ---------------- kernel B: detect dtype + dst + CSR offsets + init --------
// Per-block redundant dtype detection: sample int64-interpreted words from the
// middle of the src region (in-bounds under both interpretations). int64 =>
// hi-word 0 and lo-word < N for every sample; int32 => the "hi-word" is a
// sorted src value ~N/4 > 0 -> check fails.
__global__ void convert_kernel(const void* ei, int E, int nnodes) {
    __shared__ int s_ok;
    if (threadIdx.x == 0) s_ok = 1;
    __syncthreads();
    {
        const unsigned int* w = (const unsigned int*)ei;
        int i = E / 4 + (int)(threadIdx.x & 127);
        unsigned int lo = w[2 * i];
        unsigned int hi = w[2 * i + 1];
        if (hi != 0u || lo >= (unsigned int)nnodes) atomicAnd(&s_ok, 0);
    }
    if (blockIdx.x == 0 && threadIdx.x == 0) {
        g_tick_e = 0u;
        g_tick_n = 0u;
    }
    if (blockIdx.x == 0 && threadIdx.x < NHEAD) g_maxw[threadIdx.x] = -CUDART_INF_F;
    __syncthreads();
    const int is64 = s_ok;

    int i = blockIdx.x * blockDim.x + threadIdx.x;
    if (i >= E) return;

    int s, sp;
    if (is64) {
        const long long* p = (const long long*)ei;
        s  = (int)p[i];
        sp = (i == 0) ? -1 : (int)p[i - 1];
        g_dst[i] = (int)p[E + i];
    } else {
        const int* p = (const int*)ei;
        s  = p[i];
        sp = (i == 0) ? -1 : p[i - 1];
        g_dst[i] = p[E + i];
    }
    // CSR offsets: g_off[n] = first edge with src >= n
    for (int n = sp + 1; n <= s; n++) g_off[n] = i;
    if (i == E - 1)
        for (int n = s + 1; n <= nnodes; n++) g_off[n] = E;
}

// ---------------- kernel 1: proj = x @ W^T  (packed f32x2 FMAs) ------------
#define TM 64
#define TN 128
#define TK 32
#define BS_STRIDE (TN + 2)
#define AS_STRIDE (TM + 1)

__global__ __launch_bounds__(256) void gemm_kernel(
    const float* __restrict__ x, const float* __restrict__ W, int nrows)
{
    __shared__ float As[TK][AS_STRIDE];
    __shared__ float Bs[TK][BS_STRIDE];
    const int tid = threadIdx.x;
    const int tx = tid & 15, ty = tid >> 4;
    const int rowBase = blockIdx.x * TM;
    const int colBase = blockIdx.y * TN;

    unsigned long long acc2[4][4];
    #pragma unroll
    for (int i = 0; i < 4; i++)
        #pragma unroll
        for (int j = 0; j < 4; j++) acc2[i][j] = 0ull;

    const int lr = tid >> 5;
    const int lc = tid & 31;

    for (int k0 = 0; k0 < FIN; k0 += TK) {
        #pragma unroll
        for (int i = 0; i < 8; i++) {
            int r = lr + i * 8;
            int gr = rowBase + r;
            As[lc][r] = (gr < nrows) ? x[(size_t)gr * FIN + k0 + lc] : 0.f;
        }
        #pragma unroll
        for (int i = 0; i < 16; i++) {
            int r = lr + i * 8;
            Bs[lc][r] = W[(size_t)(colBase + r) * FIN + k0 + lc];
        }
        __syncthreads();

        #pragma unroll
        for (int kk = 0; kk < TK; kk++) {
            unsigned long long ap[4];
            #pragma unroll
            for (int i = 0; i < 4; i++) ap[i] = packdup(As[kk][ty * 4 + i]);
            unsigned long long bp[4];
            #pragma unroll
            for (int j = 0; j < 4; j++)
                bp[j] = *(const unsigned long long*)&Bs[kk][tx * 2 + j * 32];
            #pragma unroll
            for (int i = 0; i < 4; i++)
                #pragma unroll
                for (int j = 0; j < 4; j++)
                    ffma2(acc2[i][j], ap[i], bp[j]);
        }
        __syncthreads();
    }

    const float scale = (colBase == 0) ? 0.25f : 1.0f;  // q block gets FH^-0.5
    #pragma unroll
    for (int i = 0; i < 4; i++) {
        int gr = rowBase + ty * 4 + i;
        if (gr >= nrows) continue;
        #pragma unroll
        for (int j = 0; j < 4; j++) {
            float v0, v1;
            unpack2(acc2[i][j], v0, v1);
            int gc = colBase + tx * 2 + j * 32;
            g_qkv[(size_t)gr * FTOT + gc]     = v0 * scale;
            g_qkv[(size_t)gr * FTOT + gc + 1] = v1 * scale;
        }
    }
}

// ---------------- kernel 2: per-edge logits + global per-head max ----------
// Warps fetch BATCH-node tickets dynamically; per node the q row is register-
// resident and the loop streams k rows with 4-way MLP.
__global__ __launch_bounds__(256) void edge_kernel(int nnodes)
{
    const int lane = threadIdx.x & 31;
    const int h = lane >> 2;

    float runmax = -CUDART_INF_F;

    for (;;) {
        unsigned int base;
        if (lane == 0) base = atomicAdd(&g_tick_e, (unsigned int)BATCH);
        base = __shfl_sync(0xFFFFFFFFu, base, 0);
        if (base >= (unsigned int)nnodes) break;
        int nend = min((int)base + BATCH, nnodes);

        for (int n = (int)base; n < nend; n++) {
            int lo = g_off[n], hi = g_off[n + 1];
            if (hi <= lo) continue;
            const float4 qv = *(const float4*)(g_qkv + (size_t)n * FTOT + lane * 4);

            int e = lo;
            for (; e + 4 <= hi; e += 4) {
                int d0 = g_dst[e],     d1 = g_dst[e + 1];
                int d2 = g_dst[e + 2], d3 = g_dst[e + 3];
                const float4 k0 = *(const float4*)(g_qkv + (size_t)d0 * FTOT + FQK + lane * 4);
                const float4 k1 = *(const float4*)(g_qkv + (size_t)d1 * FTOT + FQK + lane * 4);
                const float4 k2 = *(const float4*)(g_qkv + (size_t)d2 * FTOT + FQK + lane * 4);
                const float4 k3 = *(const float4*)(g_qkv + (size_t)d3 * FTOT + FQK + lane * 4);
                float t0 = qv.x * k0.x + qv.y * k0.y + qv.z * k0.z + qv.w * k0.w;
                float t1 = qv.x * k1.x + qv.y * k1.y + qv.z * k1.z + qv.w * k1.w;
                float t2 = qv.x * k2.x + qv.y * k2.y + qv.z * k2.z + qv.w * k2.w;
                float t3 = qv.x * k3.x + qv.y * k3.y + qv.z * k3.z + qv.w * k3.w;
                t0 += __shfl_xor_sync(0xFFFFFFFFu, t0, 1);
                t1 += __shfl_xor_sync(0xFFFFFFFFu, t1, 1);
                t2 += __shfl_xor_sync(0xFFFFFFFFu, t2, 1);
                t3 += __shfl_xor_sync(0xFFFFFFFFu, t3, 1);
                t0 += __shfl_xor_sync(0xFFFFFFFFu, t0, 2);
                t1 += __shfl_xor_sync(0xFFFFFFFFu, t1, 2);
                t2 += __shfl_xor_sync(0xFFFFFFFFu, t2, 2);
                t3 += __shfl_xor_sync(0xFFFFFFFFu, t3, 2);
                if ((lane & 3) == 0) {
                    g_aw[(size_t)(e    ) * NHEAD + h] = t0;
                    g_aw[(size_t)(e + 1) * NHEAD + h] = t1;
                    g_aw[(size_t)(e + 2) * NHEAD + h] = t2;
                    g_aw[(size_t)(e + 3) * NHEAD + h] = t3;
                }
                runmax = fmaxf(runmax, fmaxf(fmaxf(t0, t1), fmaxf(t2, t3)));
            }
            for (; e < hi; e++) {
                int d = g_dst[e];
                const float4 kv = *(const float4*)(g_qkv + (size_t)d * FTOT + FQK + lane * 4);
                float t = qv.x * kv.x + qv.y * kv.y + qv.z * kv.z + qv.w * kv.w;
                t += __shfl_xor_sync(0xFFFFFFFFu, t, 1);
                t += __shfl_xor_sync(0xFFFFFFFFu, t, 2);
                if ((lane & 3) == 0) g_aw[(size_t)e * NHEAD + h] = t;
                runmax = fmaxf(runmax, t);
            }
        }
    }

    // hierarchical per-head max: registers -> shared -> global
    __shared__ float smax[NHEAD];
    if (threadIdx.x < NHEAD) smax[threadIdx.x] = -CUDART_INF_F;
    __syncthreads();
    if ((lane & 3) == 0 && runmax > -CUDART_INF_F) atomicMaxF(&smax[h], runmax);
    __syncthreads();
    if (threadIdx.x < NHEAD && smax[threadIdx.x] > -CUDART_INF_F)
        atomicMaxF(&g_maxw[threadIdx.x], smax[threadIdx.x]);
}

// ---------------- kernel 3: per-node softmax-weighted aggregation ----------
// Warps fetch BATCH-node tickets dynamically; CSR offsets replace the search.
__global__ __launch_bounds__(256) void node_kernel(
    float* __restrict__ out, int nnodes)
{
    const int lane = threadIdx.x & 31;
    const int h = lane >> 2;
    const float mx = g_maxw[h];

    for (;;) {
        unsigned int base;
        if (lane == 0) base = atomicAdd(&g_tick_n, (unsigned int)BATCH);
        base = __shfl_sync(0xFFFFFFFFu, base, 0);
        if (base >= (unsigned int)nnodes) break;
        int nend = min((int)base + BATCH, nnodes);

        for (int n = (int)base; n < nend; n++) {
            int lo = g_off[n], hi = g_off[n + 1];

            float4 acc = make_float4(0.f, 0.f, 0.f, 0.f);
            float sum = 0.f;

            int e = lo;
            for (; e + 4 <= hi; e += 4) {
                int d0 = g_dst[e], d1 = g_dst[e + 1], d2 = g_dst[e + 2], d3 = g_dst[e + 3];
                float a0 = g_aw[(size_t)(e    ) * NHEAD + h];
                float a1 = g_aw[(size_t)(e + 1) * NHEAD + h];
                float a2 = g_aw[(size_t)(e + 2) * NHEAD + h];
                float a3 = g_aw[(size_t)(e + 3) * NHEAD + h];
                const float4 v0 = *(const float4*)(g_qkv + (size_t)d0 * FTOT + 2 * FQK + lane * 4);
                const float4 v1 = *(const float4*)(g_qkv + (size_t)d1 * FTOT + 2 * FQK + lane * 4);
                const float4 v2 = *(const float4*)(g_qkv + (size_t)d2 * FTOT + 2 * FQK + lane * 4);
                const float4 v3 = *(const float4*)(g_qkv + (size_t)d3 * FTOT + 2 * FQK + lane * 4);
                float w0 = __expf(a0 - mx) + 1e-8f;
                float w1 = __expf(a1 - mx) + 1e-8f;
                float w2 = __expf(a2 - mx) + 1e-8f;
                float w3 = __expf(a3 - mx) + 1e-8f;
                sum += (w0 + w1) + (w2 + w3);
                acc.x += w0 * v0.x + w1 * v1.x + w2 * v2.x + w3 * v3.x;
                acc.y += w0 * v0.y + w1 * v1.y + w2 * v2.y + w3 * v3.y;
                acc.z += w0 * v0.z + w1 * v1.z + w2 * v2.z + w3 * v3.z;
                acc.w += w0 * v0.w + w1 * v1.w + w2 * v2.w + w3 * v3.w;
            }
            for (; e < hi; e++) {
                float a = g_aw[(size_t)e * NHEAD + h];
                float w = __expf(a - mx) + 1e-8f;
                sum += w;
                int d = g_dst[e];
                const float4 vv = *(const float4*)(g_qkv + (size_t)d * FTOT + 2 * FQK + lane * 4);
                acc.x += w * vv.x;
                acc.y += w * vv.y;
                acc.z += w * vv.z;
                acc.w += w * vv.w;
            }

            float inv = (hi > lo) ? (1.f / sum) : 0.f;
            float4 res = make_float4(acc.x * inv, acc.y * inv, acc.z * inv, acc.w * inv);
            ((float4*)out)[(size_t)n * 32 + lane] = res;   // coalesced 512B store
        }
    }
}

// ---------------- launch ---------------------------------------------------
extern "C" void kernel_launch(void* const* d_in, const int* in_sizes, int n_in,
                              void* d_out, int out_size)
{
    const float* x  = (const float*)d_in[0];          // [N, 128]
    const float* W  = (const float*)d_in[1];          // [384, 128]
    // d_in[2] = batch (unused by reference math)
    const void*  ei = d_in[3];                        // [2, E], int32 or int64
    float* out = (float*)d_out;

    const int nrows = in_sizes[0] / FIN;
    const int E     = in_sizes[3] / 2;

    convert_kernel<<<(E + 255) / 256, 256>>>(ei, E, nrows);

    dim3 ggrid((nrows + TM - 1) / TM, FTOT / TN);
    gemm_kernel<<<ggrid, 256>>>(x, W, nrows);

    edge_kernel<<<296, 256>>>(nrows);     // persistent-ish: 2368 warps, ticketed

    node_kernel<<<296, 256>>>(out, nrows);
}

// round 12
// speedup vs baseline: 1.3571x; 1.3571x over previous
#include <cuda_runtime.h>
#include <math_constants.h>

#define N_NODES 20000
#define N_EDGES 640000
#define FIN     128
#define FQK     128
#define FV      128
#define FTOT    384
#define NHEAD   8
#define FH      16

// ---------------- scratch (device globals; no runtime allocation) ----------
__device__ float g_qkv[N_NODES * FTOT];   // [n][0:128)=q*0.25, [128:256)=k, [256:384)=v
__device__ float g_aw [N_EDGES * NHEAD];  // per-edge per-head logits
__device__ float g_maxw[NHEAD];           // global per-head max
__device__ int   g_dst [N_EDGES];
__device__ int   g_off [N_NODES + 1];     // CSR row offsets over sorted src

// ---------------- helpers --------------------------------------------------
__device__ __forceinline__ void atomicMaxF(float* addr, float val) {
    int* ai = (int*)addr;
    int old = *ai;
    while (__int_as_float(old) < val) {
        int assumed = old;
        old = atomicCAS(ai, assumed, __float_as_int(val));
        if (old == assumed) break;
    }
}

__device__ __forceinline__ unsigned long long packdup(float a) {
    unsigned long long r;
    asm("mov.b64 %0, {%1, %1};" : "=l"(r) : "f"(a));
    return r;
}
__device__ __forceinline__ void ffma2(unsigned long long& acc,
                                      unsigned long long a, unsigned long long b) {
    asm("fma.rn.f32x2 %0, %1, %2, %0;" : "+l"(acc) : "l"(a), "l"(b));
}
__device__ __forceinline__ void unpack2(unsigned long long p, float& lo, float& hi) {
    asm("mov.b64 {%0, %1}, %2;" : "=f"(lo), "=f"(hi) : "l"(p));
}

// ---------------- kernel B: detect dtype + dst + CSR offsets + init --------
// Per-block redundant dtype detection: sample int64-interpreted words from the
// middle of the src region (in-bounds under both interpretations). int64 =>
// hi-word 0 and lo-word < N for every sample; int32 => the "hi-word" is a
// sorted src value ~N/4 > 0 -> check fails.
__global__ void convert_kernel(const void* ei, int E, int nnodes) {
    __shared__ int s_ok;
    if (threadIdx.x == 0) s_ok = 1;
    __syncthreads();
    {
        const unsigned int* w = (const unsigned int*)ei;
        int i = E / 4 + (int)(threadIdx.x & 127);
        unsigned int lo = w[2 * i];
        unsigned int hi = w[2 * i + 1];
        if (hi != 0u || lo >= (unsigned int)nnodes) atomicAnd(&s_ok, 0);
    }
    if (blockIdx.x == 0 && threadIdx.x < NHEAD) g_maxw[threadIdx.x] = -CUDART_INF_F;
    __syncthreads();
    const int is64 = s_ok;

    int i = blockIdx.x * blockDim.x + threadIdx.x;
    if (i >= E) return;

    int s, sp;
    if (is64) {
        const long long* p = (const long long*)ei;
        s  = (int)p[i];
        sp = (i == 0) ? -1 : (int)p[i - 1];
        g_dst[i] = (int)p[E + i];
    } else {
        const int* p = (const int*)ei;
        s  = p[i];
        sp = (i == 0) ? -1 : p[i - 1];
        g_dst[i] = p[E + i];
    }
    // CSR offsets: g_off[n] = first edge with src >= n
    for (int n = sp + 1; n <= s; n++) g_off[n] = i;
    if (i == E - 1)
        for (int n = s + 1; n <= nnodes; n++) g_off[n] = E;
}

// ---------------- kernel 1: proj = x @ W^T  (packed f32x2 FMAs) ------------
#define TM 64
#define TN 128
#define TK 32
#define BS_STRIDE (TN + 2)
#define AS_STRIDE (TM + 1)

__global__ __launch_bounds__(256) void gemm_kernel(
    const float* __restrict__ x, const float* __restrict__ W, int nrows)
{
    __shared__ float As[TK][AS_STRIDE];
    __shared__ float Bs[TK][BS_STRIDE];
    const int tid = threadIdx.x;
    const int tx = tid & 15, ty = tid >> 4;
    const int rowBase = blockIdx.x * TM;
    const int colBase = blockIdx.y * TN;

    unsigned long long acc2[4][4];
    #pragma unroll
    for (int i = 0; i < 4; i++)
        #pragma unroll
        for (int j = 0; j < 4; j++) acc2[i][j] = 0ull;

    const int lr = tid >> 5;
    const int lc = tid & 31;

    for (int k0 = 0; k0 < FIN; k0 += TK) {
        #pragma unroll
        for (int i = 0; i < 8; i++) {
            int r = lr + i * 8;
            int gr = rowBase + r;
            As[lc][r] = (gr < nrows) ? x[(size_t)gr * FIN + k0 + lc] : 0.f;
        }
        #pragma unroll
        for (int i = 0; i < 16; i++) {
            int r = lr + i * 8;
            Bs[lc][r] = W[(size_t)(colBase + r) * FIN + k0 + lc];
        }
        __syncthreads();

        #pragma unroll
        for (int kk = 0; kk < TK; kk++) {
            unsigned long long ap[4];
            #pragma unroll
            for (int i = 0; i < 4; i++) ap[i] = packdup(As[kk][ty * 4 + i]);
            unsigned long long bp[4];
            #pragma unroll
            for (int j = 0; j < 4; j++)
                bp[j] = *(const unsigned long long*)&Bs[kk][tx * 2 + j * 32];
            #pragma unroll
            for (int i = 0; i < 4; i++)
                #pragma unroll
                for (int j = 0; j < 4; j++)
                    ffma2(acc2[i][j], ap[i], bp[j]);
        }
        __syncthreads();
    }

    const float scale = (colBase == 0) ? 0.25f : 1.0f;  // q block gets FH^-0.5
    #pragma unroll
    for (int i = 0; i < 4; i++) {
        int gr = rowBase + ty * 4 + i;
        if (gr >= nrows) continue;
        #pragma unroll
        for (int j = 0; j < 4; j++) {
            float v0, v1;
            unpack2(acc2[i][j], v0, v1);
            int gc = colBase + tx * 2 + j * 32;
            g_qkv[(size_t)gr * FTOT + gc]     = v0 * scale;
            g_qkv[(size_t)gr * FTOT + gc + 1] = v1 * scale;
        }
    }
}

// ---------------- kernel 2: per-edge logits + global per-head max ----------
// Static map: warp w handles nodes w and w+nwarps (two independent streams).
// Per node: q row register-resident; k rows streamed with 4-way MLP.
// Lane l: head h = l>>2, floats [4l, 4l+4).
__device__ __forceinline__ float edge_logits_node(int n, int lane, int h) {
    float runmax = -CUDART_INF_F;
    int lo = g_off[n], hi = g_off[n + 1];
    if (hi <= lo) return runmax;
    const float4 qv = *(const float4*)(g_qkv + (size_t)n * FTOT + lane * 4);

    int e = lo;
    for (; e + 4 <= hi; e += 4) {
        int d0 = g_dst[e],     d1 = g_dst[e + 1];
        int d2 = g_dst[e + 2], d3 = g_dst[e + 3];
        const float4 k0 = *(const float4*)(g_qkv + (size_t)d0 * FTOT + FQK + lane * 4);
        const float4 k1 = *(const float4*)(g_qkv + (size_t)d1 * FTOT + FQK + lane * 4);
        const float4 k2 = *(const float4*)(g_qkv + (size_t)d2 * FTOT + FQK + lane * 4);
        const float4 k3 = *(const float4*)(g_qkv + (size_t)d3 * FTOT + FQK + lane * 4);
        float t0 = qv.x * k0.x + qv.y * k0.y + qv.z * k0.z + qv.w * k0.w;
        float t1 = qv.x * k1.x + qv.y * k1.y + qv.z * k1.z + qv.w * k1.w;
        float t2 = qv.x * k2.x + qv.y * k2.y + qv.z * k2.z + qv.w * k2.w;
        float t3 = qv.x * k3.x + qv.y * k3.y + qv.z * k3.z + qv.w * k3.w;
        t0 += __shfl_xor_sync(0xFFFFFFFFu, t0, 1);
        t1 += __shfl_xor_sync(0xFFFFFFFFu, t1, 1);
        t2 += __shfl_xor_sync(0xFFFFFFFFu, t2, 1);
        t3 += __shfl_xor_sync(0xFFFFFFFFu, t3, 1);
        t0 += __shfl_xor_sync(0xFFFFFFFFu, t0, 2);
        t1 += __shfl_xor_sync(0xFFFFFFFFu, t1, 2);
        t2 += __shfl_xor_sync(0xFFFFFFFFu, t2, 2);
        t3 += __shfl_xor_sync(0xFFFFFFFFu, t3, 2);
        if ((lane & 3) == 0) {
            g_aw[(size_t)(e    ) * NHEAD + h] = t0;
            g_aw[(size_t)(e + 1) * NHEAD + h] = t1;
            g_aw[(size_t)(e + 2) * NHEAD + h] = t2;
            g_aw[(size_t)(e + 3) * NHEAD + h] = t3;
        }
        runmax = fmaxf(runmax, fmaxf(fmaxf(t0, t1), fmaxf(t2, t3)));
    }
    for (; e < hi; e++) {
        int d = g_dst[e];
        const float4 kv = *(const float4*)(g_qkv + (size_t)d * FTOT + FQK + lane * 4);
        float t = qv.x * kv.x + qv.y * kv.y + qv.z * kv.z + qv.w * kv.w;
        t += __shfl_xor_sync(0xFFFFFFFFu, t, 1);
        t += __shfl_xor_sync(0xFFFFFFFFu, t, 2);
        if ((lane & 3) == 0) g_aw[(size_t)e * NHEAD + h] = t;
        runmax = fmaxf(runmax, t);
    }
    return runmax;
}

__global__ __launch_bounds__(256) void edge_kernel(int nnodes)
{
    const int lane   = threadIdx.x & 31;
    const int warp   = (blockIdx.x * blockDim.x + threadIdx.x) >> 5;
    const int nwarps = (gridDim.x * blockDim.x) >> 5;
    const int h = lane >> 2;

    float runmax = -CUDART_INF_F;
    for (int n = warp; n < nnodes; n += nwarps)
        runmax = fmaxf(runmax, edge_logits_node(n, lane, h));

    // hierarchical per-head max: registers -> shared -> global
    __shared__ float smax[NHEAD];
    if (threadIdx.x < NHEAD) smax[threadIdx.x] = -CUDART_INF_F;
    __syncthreads();
    if ((lane & 3) == 0 && runmax > -CUDART_INF_F) atomicMaxF(&smax[h], runmax);
    __syncthreads();
    if (threadIdx.x < NHEAD && smax[threadIdx.x] > -CUDART_INF_F)
        atomicMaxF(&g_maxw[threadIdx.x], smax[threadIdx.x]);
}

// ---------------- kernel 3: per-node softmax-weighted aggregation ----------
// Static map: warp w handles nodes w and w+nwarps.
__device__ __forceinline__ void node_aggregate(int n, int lane, int h, float mx,
                                               float* __restrict__ out) {
    int lo = g_off[n], hi = g_off[n + 1];

    float4 acc = make_float4(0.f, 0.f, 0.f, 0.f);
    float sum = 0.f;

    int e = lo;
    for (; e + 4 <= hi; e += 4) {
        int d0 = g_dst[e], d1 = g_dst[e + 1], d2 = g_dst[e + 2], d3 = g_dst[e + 3];
        float a0 = g_aw[(size_t)(e    ) * NHEAD + h];
        float a1 = g_aw[(size_t)(e + 1) * NHEAD + h];
        float a2 = g_aw[(size_t)(e + 2) * NHEAD + h];
        float a3 = g_aw[(size_t)(e + 3) * NHEAD + h];
        const float4 v0 = *(const float4*)(g_qkv + (size_t)d0 * FTOT + 2 * FQK + lane * 4);
        const float4 v1 = *(const float4*)(g_qkv + (size_t)d1 * FTOT + 2 * FQK + lane * 4);
        const float4 v2 = *(const float4*)(g_qkv + (size_t)d2 * FTOT + 2 * FQK + lane * 4);
        const float4 v3 = *(const float4*)(g_qkv + (size_t)d3 * FTOT + 2 * FQK + lane * 4);
        float w0 = __expf(a0 - mx) + 1e-8f;
        float w1 = __expf(a1 - mx) + 1e-8f;
        float w2 = __expf(a2 - mx) + 1e-8f;
        float w3 = __expf(a3 - mx) + 1e-8f;
        sum += (w0 + w1) + (w2 + w3);
        acc.x += w0 * v0.x + w1 * v1.x + w2 * v2.x + w3 * v3.x;
        acc.y += w0 * v0.y + w1 * v1.y + w2 * v2.y + w3 * v3.y;
        acc.z += w0 * v0.z + w1 * v1.z + w2 * v2.z + w3 * v3.z;
        acc.w += w0 * v0.w + w1 * v1.w + w2 * v2.w + w3 * v3.w;
    }
    for (; e < hi; e++) {
        float a = g_aw[(size_t)e * NHEAD + h];
        float w = __expf(a - mx) + 1e-8f;
        sum += w;
        int d = g_dst[e];
        const float4 vv = *(const float4*)(g_qkv + (size_t)d * FTOT + 2 * FQK + lane * 4);
        acc.x += w * vv.x;
        acc.y += w * vv.y;
        acc.z += w * vv.z;
        acc.w += w * vv.w;
    }

    float inv = (hi > lo) ? (1.f / sum) : 0.f;
    float4 res = make_float4(acc.x * inv, acc.y * inv, acc.z * inv, acc.w * inv);
    ((float4*)out)[(size_t)n * 32 + lane] = res;   // coalesced 512B store
}

__global__ __launch_bounds__(256) void node_kernel(
    float* __restrict__ out, int nnodes)
{
    const int lane   = threadIdx.x & 31;
    const int warp   = (blockIdx.x * blockDim.x + threadIdx.x) >> 5;
    const int nwarps = (gridDim.x * blockDim.x) >> 5;
    const int h = lane >> 2;
    const float mx = g_maxw[h];

    for (int n = warp; n < nnodes; n += nwarps)
        node_aggregate(n, lane, h, mx, out);
}

// ---------------- launch ---------------------------------------------------
extern "C" void kernel_launch(void* const* d_in, const int* in_sizes, int n_in,
                              void* d_out, int out_size)
{
    const float* x  = (const float*)d_in[0];          // [N, 128]
    const float* W  = (const float*)d_in[1];          // [384, 128]
    // d_in[2] = batch (unused by reference math)
    const void*  ei = d_in[3];                        // [2, E], int32 or int64
    float* out = (float*)d_out;

    const int nrows = in_sizes[0] / FIN;
    const int E     = in_sizes[3] / 2;

    convert_kernel<<<(E + 255) / 256, 256>>>(ei, E, nrows);

    dim3 ggrid((nrows + TM - 1) / TM, FTOT / TN);
    gemm_kernel<<<ggrid, 256>>>(x, W, nrows);

    // one wave: 148 SMs * 8 CTAs? -> use 1250 blocks (=10000 warps, 2 nodes/warp)
    edge_kernel<<<1250, 256>>>(nrows);

    node_kernel<<<1250, 256>>>(out, nrows);
}